// round 12
// baseline (speedup 1.0000x reference)
#include <cuda_runtime.h>
#include <cuda_fp16.h>
#include <math.h>

constexpr int BB = 8;
constexpr int TT = 128;
constexpr int NN = 256;
constexpr int FF = 128;
constexpr int MTOT = BB * TT * NN;   // 262144
constexpr int HP = 136;              // smem half pitch (padded)

// -------- scratch (device globals) --------
__device__ __half g_attn[MTOT * FF];
// ALL weights transposed [n][k] fp16 (B-fragments via LDG)
__device__ __align__(16) __half g_wqT [FF * FF];
__device__ __align__(16) __half g_wkhT[FF * FF];
__device__ __align__(16) __half g_wvhT[FF * FF];
__device__ __align__(16) __half g_woT [FF * FF];
__device__ __align__(16) __half g_wf1T[FF * FF];
__device__ __align__(16) __half g_wf2T[FF * FF];

// ------------------- asm helpers -------------------
__device__ __forceinline__ unsigned sptr(const void* ptr) {
    return (unsigned)__cvta_generic_to_shared(ptr);
}
__device__ __forceinline__ void ldsm4(unsigned& r0, unsigned& r1, unsigned& r2, unsigned& r3, unsigned addr) {
    asm volatile("ldmatrix.sync.aligned.m8n8.x4.shared.b16 {%0,%1,%2,%3},[%4];"
                 : "=r"(r0), "=r"(r1), "=r"(r2), "=r"(r3) : "r"(addr));
}
__device__ __forceinline__ void ldsm4t(unsigned& r0, unsigned& r1, unsigned& r2, unsigned& r3, unsigned addr) {
    asm volatile("ldmatrix.sync.aligned.m8n8.x4.trans.shared.b16 {%0,%1,%2,%3},[%4];"
                 : "=r"(r0), "=r"(r1), "=r"(r2), "=r"(r3) : "r"(addr));
}
__device__ __forceinline__ void mma16816(float* cc, const unsigned* aa, const unsigned* bb) {
    asm volatile("mma.sync.aligned.m16n8k16.row.col.f32.f16.f16.f32 "
                 "{%0,%1,%2,%3},{%4,%5,%6,%7},{%8,%9},{%0,%1,%2,%3};"
                 : "+f"(cc[0]), "+f"(cc[1]), "+f"(cc[2]), "+f"(cc[3])
                 : "r"(aa[0]), "r"(aa[1]), "r"(aa[2]), "r"(aa[3]), "r"(bb[0]), "r"(bb[1]));
}
__device__ __forceinline__ unsigned pack2(float a, float b) {
    __half2 h = __floats2half2_rn(a, b);
    return *reinterpret_cast<unsigned*>(&h);
}
__device__ __forceinline__ void cpa16(void* dst, const void* src) {
    asm volatile("cp.async.cg.shared.global [%0], [%1], 16;"
                 :: "r"(sptr(dst)), "l"(src));
}
__device__ __forceinline__ void cpcommit() {
    asm volatile("cp.async.commit_group;");
}
template<int N> __device__ __forceinline__ void cpwait() {
    asm volatile("cp.async.wait_group %0;" :: "n"(N));
}

// ---------- 256-thread tile GEMM, B-fragments via LDG from transposed weight ----------
// Wt layout: [n][k]. b0 = {Wt[n][k0+2tig], +1}, b1 = same +8, n = wx*32 + j*8 + gid.
__device__ __forceinline__ void mma_tile_ldg(const __half* Amat, const __half* __restrict__ Wt,
                                             float acc[4][4][4]) {
    const int lane = threadIdx.x & 31;
    const int warp = threadIdx.x >> 5;
    const int wy = warp >> 2;
    const int wx = warp & 3;
    const int r16 = lane & 15;
    const int hi8 = (lane >> 4) * 8;
    const int gid = lane >> 2;
    const int tig = lane & 3;
    const __half* bbase = Wt + (wx * 32 + gid) * 128 + tig * 2;
    #pragma unroll
    for (int k0 = 0; k0 < 128; k0 += 16) {
        unsigned afrag[4][4];
        #pragma unroll
        for (int i = 0; i < 4; ++i) {
            unsigned addr = sptr(Amat + (wy * 64 + i * 16 + r16) * HP + k0 + hi8);
            ldsm4(afrag[i][0], afrag[i][1], afrag[i][2], afrag[i][3], addr);
        }
        unsigned bfrag[4][2];
        #pragma unroll
        for (int j = 0; j < 4; ++j) {
            const __half* bp = bbase + j * 8 * 128 + k0;
            bfrag[j][0] = *(const unsigned*)(bp);
            bfrag[j][1] = *(const unsigned*)(bp + 8);
        }
        #pragma unroll
        for (int i = 0; i < 4; ++i)
            #pragma unroll
            for (int j = 0; j < 4; ++j)
                mma16816(acc[i][j], afrag[i], bfrag[j]);
    }
}

// writeback accumulators (+bias, optional relu) into an f16 smem tile [128][HP]
__device__ __forceinline__ void store_tile(__half* dst, float acc[4][4][4],
                                           const float* __restrict__ bias, bool doRelu) {
    const int lane = threadIdx.x & 31;
    const int warp = threadIdx.x >> 5;
    const int wy = warp >> 2;
    const int wx = warp & 3;
    const int gid = lane >> 2;
    const int tig = lane & 3;
    #pragma unroll
    for (int i = 0; i < 4; ++i) {
        int row = wy * 64 + i * 16 + gid;
        #pragma unroll
        for (int j = 0; j < 4; ++j) {
            int col = wx * 32 + j * 8 + tig * 2;
            float2 bv = *(const float2*)(bias + col);
            float o0 = acc[i][j][0] + bv.x;
            float o1 = acc[i][j][1] + bv.y;
            float o2 = acc[i][j][2] + bv.x;
            float o3 = acc[i][j][3] + bv.y;
            if (doRelu) {
                o0 = fmaxf(o0, 0.f); o1 = fmaxf(o1, 0.f);
                o2 = fmaxf(o2, 0.f); o3 = fmaxf(o3, 0.f);
            }
            *(__half2*)(dst + row * HP + col)       = __floats2half2_rn(o0, o1);
            *(__half2*)(dst + (row + 8) * HP + col) = __floats2half2_rn(o2, o3);
        }
    }
}

// =====================================================================
// Kernel 0: fp32 -> fp16 weight conversion, ALL transposed [n][k].
// =====================================================================
__global__ void conv_kernel(const float* __restrict__ Wq, const float* __restrict__ Wkh,
                            const float* __restrict__ Wvh, const float* __restrict__ Wo,
                            const float* __restrict__ Wf1, const float* __restrict__ Wf2)
{
    int i = blockIdx.x * 256 + threadIdx.x;   // [0, 4096): one float4 per matrix
    int krow = i >> 5;                        // k row in fp32 [k][n]
    int n0 = (i & 31) * 4;                    // starting n column
    float4 a;

    a = ((const float4*)Wq)[i];
    g_wqT[(n0 + 0) * 128 + krow] = __float2half(a.x);
    g_wqT[(n0 + 1) * 128 + krow] = __float2half(a.y);
    g_wqT[(n0 + 2) * 128 + krow] = __float2half(a.z);
    g_wqT[(n0 + 3) * 128 + krow] = __float2half(a.w);

    a = ((const float4*)Wkh)[i];
    g_wkhT[(n0 + 0) * 128 + krow] = __float2half(a.x);
    g_wkhT[(n0 + 1) * 128 + krow] = __float2half(a.y);
    g_wkhT[(n0 + 2) * 128 + krow] = __float2half(a.z);
    g_wkhT[(n0 + 3) * 128 + krow] = __float2half(a.w);

    a = ((const float4*)Wvh)[i];
    g_wvhT[(n0 + 0) * 128 + krow] = __float2half(a.x);
    g_wvhT[(n0 + 1) * 128 + krow] = __float2half(a.y);
    g_wvhT[(n0 + 2) * 128 + krow] = __float2half(a.z);
    g_wvhT[(n0 + 3) * 128 + krow] = __float2half(a.w);

    a = ((const float4*)Wo)[i];
    g_woT[(n0 + 0) * 128 + krow] = __float2half(a.x);
    g_woT[(n0 + 1) * 128 + krow] = __float2half(a.y);
    g_woT[(n0 + 2) * 128 + krow] = __float2half(a.z);
    g_woT[(n0 + 3) * 128 + krow] = __float2half(a.w);

    a = ((const float4*)Wf1)[i];
    g_wf1T[(n0 + 0) * 128 + krow] = __float2half(a.x);
    g_wf1T[(n0 + 1) * 128 + krow] = __float2half(a.y);
    g_wf1T[(n0 + 2) * 128 + krow] = __float2half(a.z);
    g_wf1T[(n0 + 3) * 128 + krow] = __float2half(a.w);

    a = ((const float4*)Wf2)[i];
    g_wf2T[(n0 + 0) * 128 + krow] = __float2half(a.x);
    g_wf2T[(n0 + 1) * 128 + krow] = __float2half(a.y);
    g_wf2T[(n0 + 2) * 128 + krow] = __float2half(a.z);
    g_wf2T[(n0 + 3) * 128 + krow] = __float2half(a.w);
}

// =====================================================================
// Attention warp body (unchanged from R11).
// =====================================================================
template<int NP>
__device__ __forceinline__ void attn_warp(const __half* Qs, const __half* Ks, const __half* Vs,
                                          int base, int w, int lane)
{
    const int r16 = lane & 15;
    const int hi8 = (lane >> 4) * 8;
    const int gid = lane >> 2;
    const int tig = lane & 3;

    unsigned aq[8][4];
    #pragma unroll
    for (int k = 0; k < 8; ++k) {
        unsigned addr = sptr(Qs + (16 * w + r16) * HP + k * 16 + hi8);
        ldsm4(aq[k][0], aq[k][1], aq[k][2], aq[k][3], addr);
    }

    float c[2 * NP][4];
    #pragma unroll
    for (int js = 0; js < 2 * NP; ++js) {
        c[js][0] = 0.f; c[js][1] = 0.f; c[js][2] = 0.f; c[js][3] = 0.f;
    }
    #pragma unroll
    for (int jp = 0; jp < NP; ++jp) {
        #pragma unroll
        for (int k = 0; k < 8; ++k) {
            unsigned t0, t1, t2, t3;
            unsigned addr = sptr(Ks + (16 * jp + r16) * HP + k * 16 + hi8);
            ldsm4(t0, t1, t2, t3, addr);
            unsigned bE[2] = { t0, t2 };
            unsigned bO[2] = { t1, t3 };
            mma16816(c[2 * jp],     aq[k], bE);
            mma16816(c[2 * jp + 1], aq[k], bO);
        }
    }

    const float scale = 0.08838834764831845f;   // 1/sqrt(128)
    const int tlo = 16 * w + gid;
    const int thi = tlo + 8;
    float mlo = -1e30f, mhi = -1e30f;
    #pragma unroll
    for (int js = 0; js < 2 * NP; ++js) {
        int s0 = 8 * js + 2 * tig;
        int s1 = s0 + 1;
        c[js][0] *= scale; c[js][1] *= scale;
        c[js][2] *= scale; c[js][3] *= scale;
        if (js >= 2 * NP - 2) {          // diagonal block: causal mask
            if (s0 > tlo) c[js][0] = -1e30f;
            if (s1 > tlo) c[js][1] = -1e30f;
            if (s0 > thi) c[js][2] = -1e30f;
            if (s1 > thi) c[js][3] = -1e30f;
        }
        mlo = fmaxf(mlo, fmaxf(c[js][0], c[js][1]));
        mhi = fmaxf(mhi, fmaxf(c[js][2], c[js][3]));
    }
    #pragma unroll
    for (int o = 1; o <= 2; o <<= 1) {
        mlo = fmaxf(mlo, __shfl_xor_sync(0xffffffffu, mlo, o));
        mhi = fmaxf(mhi, __shfl_xor_sync(0xffffffffu, mhi, o));
    }
    float slo = 0.f, shi = 0.f;
    #pragma unroll
    for (int js = 0; js < 2 * NP; ++js) {
        c[js][0] = __expf(c[js][0] - mlo);
        c[js][1] = __expf(c[js][1] - mlo);
        c[js][2] = __expf(c[js][2] - mhi);
        c[js][3] = __expf(c[js][3] - mhi);
        slo += c[js][0] + c[js][1];
        shi += c[js][2] + c[js][3];
    }
    #pragma unroll
    for (int o = 1; o <= 2; o <<= 1) {
        slo += __shfl_xor_sync(0xffffffffu, slo, o);
        shi += __shfl_xor_sync(0xffffffffu, shi, o);
    }
    const float invlo = 1.f / slo;
    const float invhi = 1.f / shi;

    float ov[16][4];
    #pragma unroll
    for (int jt = 0; jt < 16; ++jt) {
        ov[jt][0] = 0.f; ov[jt][1] = 0.f; ov[jt][2] = 0.f; ov[jt][3] = 0.f;
    }
    #pragma unroll
    for (int ks = 0; ks < NP; ++ks) {
        unsigned ap[4];
        ap[0] = pack2(c[2 * ks][0],     c[2 * ks][1]);
        ap[1] = pack2(c[2 * ks][2],     c[2 * ks][3]);
        ap[2] = pack2(c[2 * ks + 1][0], c[2 * ks + 1][1]);
        ap[3] = pack2(c[2 * ks + 1][2], c[2 * ks + 1][3]);
        #pragma unroll
        for (int jf = 0; jf < 8; ++jf) {
            unsigned t0, t1, t2, t3;
            unsigned addr = sptr(Vs + (16 * ks + r16) * HP + jf * 16 + hi8);
            ldsm4t(t0, t1, t2, t3, addr);
            unsigned b0[2] = { t0, t1 };
            unsigned b1[2] = { t2, t3 };
            mma16816(ov[2 * jf],     ap, b0);
            mma16816(ov[2 * jf + 1], ap, b1);
        }
    }

    __half* olo = g_attn + (base + tlo * NN) * FF;
    __half* ohi = g_attn + (base + thi * NN) * FF;
    #pragma unroll
    for (int jt = 0; jt < 16; ++jt) {
        int col = jt * 8 + tig * 2;
        *(__half2*)(olo + col) = __floats2half2_rn(ov[jt][0] * invlo, ov[jt][1] * invlo);
        *(__half2*)(ohi + col) = __floats2half2_rn(ov[jt][2] * invhi, ov[jt][3] * invhi);
    }
}

// =====================================================================
// Kernel 1 (fused qkv + attention), 256 threads, 2 CTAs/SM (unchanged R11).
// =====================================================================
__global__ __launch_bounds__(256, 2) void fused_attn_kernel(
    const float* __restrict__ xl, const float* __restrict__ xh,
    const float* __restrict__ te,
    const float* __restrict__ bq, const float* __restrict__ bkh,
    const float* __restrict__ bvh)
{
    extern __shared__ char smraw[];
    __half* X1 = (__half*)smraw;          // xh+te -> later K
    __half* X2 = X1 + 128 * HP;           // xl+te -> later Q
    __half* C  = X2 + 128 * HP;           // V

    const int head = blockIdx.x;
    const int bidx = head >> 8;
    const int nidx = head & 255;
    const int base = bidx * TT * NN + nidx;

    const int tid = threadIdx.x;
    const int w = tid >> 5;
    const int lane = tid & 31;

    const float4* xl4 = (const float4*)xl;
    const float4* xh4 = (const float4*)xh;
    const float4* te4 = (const float4*)te;

    #pragma unroll
    for (int v = tid; v < 4096; v += 256) {
        int row = v >> 5;
        int c4 = v & 31;
        float4 tval = te4[(bidx * TT + row) * 32 + c4];
        float4 ah = xh4[(base + row * NN) * 32 + c4];
        __half2* dh = (__half2*)(X1 + row * HP + c4 * 4);
        dh[0] = __floats2half2_rn(ah.x + tval.x, ah.y + tval.y);
        dh[1] = __floats2half2_rn(ah.z + tval.z, ah.w + tval.w);
        float4 al = xl4[(base + row * NN) * 32 + c4];
        __half2* dl = (__half2*)(X2 + row * HP + c4 * 4);
        dl[0] = __floats2half2_rn(al.x + tval.x, al.y + tval.y);
        dl[1] = __floats2half2_rn(al.z + tval.z, al.w + tval.w);
    }
    __syncthreads();

    {
        float accV[4][4][4] = {};
        mma_tile_ldg(X1, g_wvhT, accV);
        store_tile(C, accV, bvh, true);
    }
    {
        float accK[4][4][4] = {};
        mma_tile_ldg(X1, g_wkhT, accK);
        __syncthreads();                 // all X1 reads done
        store_tile(X1, accK, bkh, true); // K -> X1
    }
    {
        float accQ[4][4][4] = {};
        mma_tile_ldg(X2, g_wqT, accQ);
        __syncthreads();                 // all X2 reads done; K store visible
        store_tile(X2, accQ, bq, false); // Q -> X2
    }
    __syncthreads();                     // Q/K/V visible

    switch (w) {
        case 0: attn_warp<1>(X2, X1, C, base, 0, lane); break;
        case 1: attn_warp<2>(X2, X1, C, base, 1, lane); break;
        case 2: attn_warp<3>(X2, X1, C, base, 2, lane); break;
        case 3: attn_warp<4>(X2, X1, C, base, 3, lane); break;
        case 4: attn_warp<5>(X2, X1, C, base, 4, lane); break;
        case 5: attn_warp<6>(X2, X1, C, base, 5, lane); break;
        case 6: attn_warp<7>(X2, X1, C, base, 6, lane); break;
        default: attn_warp<8>(X2, X1, C, base, 7, lane); break;
    }
}

// =====================================================================
// Kernel 2 (fused proj+ffn), 256 threads, 2 CTAs/SM.
// All weights via LDG (transposed globals); only attn tile staged.
// A1 = attn -> ln1 (f16); A2 = h.
// =====================================================================
__global__ __launch_bounds__(256, 2) void tail_kernel(
    float* __restrict__ outp,
    const float* __restrict__ xl, const float* __restrict__ te,
    const float* __restrict__ bo, const float* __restrict__ bf1,
    const float* __restrict__ bf2)
{
    extern __shared__ char smraw[];
    __half* A1 = (__half*)smraw;          // attn -> ln1 (f16)
    __half* A2 = A1 + 128 * HP;           // h
    float* red1 = (float*)(A2 + 128 * HP);   // [128][4] sums
    float* red2 = red1 + 512;                // [128][4] sumsq

    const int m0 = blockIdx.x * 128;
    const int tid = threadIdx.x;
    const float* teRow = te + (m0 / NN) * FF;

    // stage attn tile via cp.async
    #pragma unroll
    for (int v = tid; v < 2048; v += 256) {
        int row = v >> 4;
        int q16 = v & 15;
        cpa16(A1 + row * HP + q16 * 8, ((const uint4*)(g_attn + (m0 + row) * FF)) + q16);
    }
    cpcommit();
    cpwait<0>();
    __syncthreads();

    const int lane = tid & 31;
    const int warp = tid >> 5;
    const int wy = warp >> 2;
    const int wx = warp & 3;
    const int gid = lane >> 2;
    const int tig = lane & 3;

    // ---- proj GEMM (Wo via LDG) ----
    float acc[4][4][4] = {};
    mma_tile_ldg(A1, g_woT, acc);

    // ---- val = acc + bo + xl + te ; LN1 partials ----
    #pragma unroll
    for (int i = 0; i < 4; ++i) {
        int rlo = wy * 64 + i * 16 + gid;
        int rhi = rlo + 8;
        float s1lo = 0.f, s2lo = 0.f, s1hi = 0.f, s2hi = 0.f;
        #pragma unroll
        for (int j = 0; j < 4; ++j) {
            int col = wx * 32 + j * 8 + tig * 2;
            float2 bv = *(const float2*)(bo + col);
            float2 x0 = *(const float2*)(xl + (m0 + rlo) * FF + col);
            float2 x1 = *(const float2*)(xl + (m0 + rhi) * FF + col);
            float2 t0 = *(const float2*)(teRow + col);
            float v0 = acc[i][j][0] + bv.x + x0.x + t0.x;
            float v1 = acc[i][j][1] + bv.y + x0.y + t0.y;
            float v2 = acc[i][j][2] + bv.x + x1.x + t0.x;
            float v3 = acc[i][j][3] + bv.y + x1.y + t0.y;
            acc[i][j][0] = v0; acc[i][j][1] = v1;
            acc[i][j][2] = v2; acc[i][j][3] = v3;
            s1lo += v0 + v1; s2lo += v0 * v0 + v1 * v1;
            s1hi += v2 + v3; s2hi += v2 * v2 + v3 * v3;
        }
        #pragma unroll
        for (int o = 1; o <= 2; o <<= 1) {
            s1lo += __shfl_xor_sync(0xffffffffu, s1lo, o);
            s2lo += __shfl_xor_sync(0xffffffffu, s2lo, o);
            s1hi += __shfl_xor_sync(0xffffffffu, s1hi, o);
            s2hi += __shfl_xor_sync(0xffffffffu, s2hi, o);
        }
        if (tig == 0) {
            red1[rlo * 4 + wx] = s1lo; red2[rlo * 4 + wx] = s2lo;
            red1[rhi * 4 + wx] = s1hi; red2[rhi * 4 + wx] = s2hi;
        }
    }
    __syncthreads();   // A1 reads (proj GEMM) done + red visible

    // ---- LN1 finalize -> ln1 (f16) into A1 ----
    #pragma unroll
    for (int i = 0; i < 4; ++i) {
        int rlo = wy * 64 + i * 16 + gid;
        int rhi = rlo + 8;
        float mlo = (red1[rlo * 4] + red1[rlo * 4 + 1] + red1[rlo * 4 + 2] + red1[rlo * 4 + 3]) * 0.0078125f;
        float vlo = (red2[rlo * 4] + red2[rlo * 4 + 1] + red2[rlo * 4 + 2] + red2[rlo * 4 + 3]) * 0.0078125f - mlo * mlo;
        float rslo = rsqrtf(vlo + 1e-5f);
        float mhi = (red1[rhi * 4] + red1[rhi * 4 + 1] + red1[rhi * 4 + 2] + red1[rhi * 4 + 3]) * 0.0078125f;
        float vhi = (red2[rhi * 4] + red2[rhi * 4 + 1] + red2[rhi * 4 + 2] + red2[rhi * 4 + 3]) * 0.0078125f - mhi * mhi;
        float rshi = rsqrtf(vhi + 1e-5f);
        #pragma unroll
        for (int j = 0; j < 4; ++j) {
            int col = wx * 32 + j * 8 + tig * 2;
            *(__half2*)(A1 + rlo * HP + col) =
                __floats2half2_rn((acc[i][j][0] - mlo) * rslo, (acc[i][j][1] - mlo) * rslo);
            *(__half2*)(A1 + rhi * HP + col) =
                __floats2half2_rn((acc[i][j][2] - mhi) * rshi, (acc[i][j][3] - mhi) * rshi);
        }
    }
    __syncthreads();   // ln1 visible

    // ---- FFN GEMM 1 (Wf1 via LDG): h = relu(ln1 @ Wf1 + bf1) -> A2 ----
    float acc2[4][4][4] = {};
    mma_tile_ldg(A1, g_wf1T, acc2);
    store_tile(A2, acc2, bf1, true);
    __syncthreads();   // h visible

    // ---- FFN GEMM 2 (Wf2 via LDG) ----
    float acc3[4][4][4] = {};
    mma_tile_ldg(A2, g_wf2T, acc3);

    // ---- acc3 += bf2 + ln1(A1); LN2 partials ----
    #pragma unroll
    for (int i = 0; i < 4; ++i) {
        int rlo = wy * 64 + i * 16 + gid;
        int rhi = rlo + 8;
        float s1lo = 0.f, s2lo = 0.f, s1hi = 0.f, s2hi = 0.f;
        #pragma unroll
        for (int j = 0; j < 4; ++j) {
            int col = wx * 32 + j * 8 + tig * 2;
            float2 bv = *(const float2*)(bf2 + col);
            float2 l0 = __half22float2(*(const __half2*)(A1 + rlo * HP + col));
            float2 l1 = __half22float2(*(const __half2*)(A1 + rhi * HP + col));
            float v0 = acc3[i][j][0] + bv.x + l0.x;
            float v1 = acc3[i][j][1] + bv.y + l0.y;
            float v2 = acc3[i][j][2] + bv.x + l1.x;
            float v3 = acc3[i][j][3] + bv.y + l1.y;
            acc3[i][j][0] = v0; acc3[i][j][1] = v1;
            acc3[i][j][2] = v2; acc3[i][j][3] = v3;
            s1lo += v0 + v1; s2lo += v0 * v0 + v1 * v1;
            s1hi += v2 + v3; s2hi += v2 * v2 + v3 * v3;
        }
        #pragma unroll
        for (int o = 1; o <= 2; o <<= 1) {
            s1lo += __shfl_xor_sync(0xffffffffu, s1lo, o);
            s2lo += __shfl_xor_sync(0xffffffffu, s2lo, o);
            s1hi += __shfl_xor_sync(0xffffffffu, s1hi, o);
            s2hi += __shfl_xor_sync(0xffffffffu, s2hi, o);
        }
        if (tig == 0) {
            red1[rlo * 4 + wx] = s1lo; red2[rlo * 4 + wx] = s2lo;
            red1[rhi * 4 + wx] = s1hi; red2[rhi * 4 + wx] = s2hi;
        }
    }
    __syncthreads();

    // ---- LN2 finalize -> output ----
    #pragma unroll
    for (int i = 0; i < 4; ++i) {
        int rlo = wy * 64 + i * 16 + gid;
        int rhi = rlo + 8;
        float mlo = (red1[rlo * 4] + red1[rlo * 4 + 1] + red1[rlo * 4 + 2] + red1[rlo * 4 + 3]) * 0.0078125f;
        float vlo = (red2[rlo * 4] + red2[rlo * 4 + 1] + red2[rlo * 4 + 2] + red2[rlo * 4 + 3]) * 0.0078125f - mlo * mlo;
        float rslo = rsqrtf(vlo + 1e-5f);
        float mhi = (red1[rhi * 4] + red1[rhi * 4 + 1] + red1[rhi * 4 + 2] + red1[rhi * 4 + 3]) * 0.0078125f;
        float vhi = (red2[rhi * 4] + red2[rhi * 4 + 1] + red2[rhi * 4 + 2] + red2[rhi * 4 + 3]) * 0.0078125f - mhi * mhi;
        float rshi = rsqrtf(vhi + 1e-5f);
        #pragma unroll
        for (int j = 0; j < 4; ++j) {
            int col = wx * 32 + j * 8 + tig * 2;
            float2 o0, o1;
            o0.x = (acc3[i][j][0] - mlo) * rslo;
            o0.y = (acc3[i][j][1] - mlo) * rslo;
            o1.x = (acc3[i][j][2] - mhi) * rshi;
            o1.y = (acc3[i][j][3] - mhi) * rshi;
            *(float2*)(outp + (m0 + rlo) * FF + col) = o0;
            *(float2*)(outp + (m0 + rhi) * FF + col) = o1;
        }
    }
}

// =====================================================================
extern "C" void kernel_launch(void* const* d_in, const int* in_sizes, int n_in,
                              void* d_out, int out_size)
{
    const float* xl  = (const float*)d_in[0];
    const float* xh  = (const float*)d_in[1];
    const float* te  = (const float*)d_in[2];
    const float* Wq  = (const float*)d_in[3];
    const float* bq  = (const float*)d_in[4];
    const float* Wkh = (const float*)d_in[5];
    const float* bkh = (const float*)d_in[6];
    const float* Wvh = (const float*)d_in[7];
    const float* bvh = (const float*)d_in[8];
    const float* Wo  = (const float*)d_in[9];
    const float* bo  = (const float*)d_in[10];
    const float* Wf1 = (const float*)d_in[11];
    const float* bf1 = (const float*)d_in[12];
    const float* Wf2 = (const float*)d_in[13];
    const float* bf2 = (const float*)d_in[14];
    float* outp = (float*)d_out;

    const int smFused = 3 * 128 * HP * 2;                     // 104448
    const int smTail  = 2 * 128 * HP * 2 + 4096;              // 73728

    cudaFuncSetAttribute(fused_attn_kernel, cudaFuncAttributeMaxDynamicSharedMemorySize, smFused);
    cudaFuncSetAttribute(tail_kernel,       cudaFuncAttributeMaxDynamicSharedMemorySize, smTail);

    conv_kernel<<<16, 256>>>(Wq, Wkh, Wvh, Wo, Wf1, Wf2);
    fused_attn_kernel<<<BB * NN, 256, smFused>>>(xl, xh, te, bq, bkh, bvh);
    tail_kernel<<<MTOT / 128, 256, smTail>>>(outp, xl, te, bo, bf1, bf2);
}

// round 13
// speedup vs baseline: 1.2680x; 1.2680x over previous
#include <cuda_runtime.h>
#include <cuda_fp16.h>
#include <math.h>

constexpr int BB = 8;
constexpr int TT = 128;
constexpr int NN = 256;
constexpr int FF = 128;
constexpr int MTOT = BB * TT * NN;   // 262144
constexpr int HP = 136;              // smem half pitch (padded)

// -------- scratch (device globals) --------
__device__ __half g_attn[MTOT * FF];
// packed fragment-order weights: [wx][k0step][lane][j] -> uint2 {b0, b1}
// b0 = half2(W[k0+2tig][n], W[k0+2tig+1][n]); b1 = same +8; n = wx*32+j*8+gid
__device__ __align__(16) uint2 g_pq [4096];
__device__ __align__(16) uint2 g_pkh[4096];
__device__ __align__(16) uint2 g_pvh[4096];
__device__ __align__(16) uint2 g_po [4096];
__device__ __align__(16) uint2 g_pf1[4096];
__device__ __align__(16) uint2 g_pf2[4096];

// ------------------- asm helpers -------------------
__device__ __forceinline__ unsigned sptr(const void* ptr) {
    return (unsigned)__cvta_generic_to_shared(ptr);
}
__device__ __forceinline__ void ldsm4(unsigned& r0, unsigned& r1, unsigned& r2, unsigned& r3, unsigned addr) {
    asm volatile("ldmatrix.sync.aligned.m8n8.x4.shared.b16 {%0,%1,%2,%3},[%4];"
                 : "=r"(r0), "=r"(r1), "=r"(r2), "=r"(r3) : "r"(addr));
}
__device__ __forceinline__ void ldsm4t(unsigned& r0, unsigned& r1, unsigned& r2, unsigned& r3, unsigned addr) {
    asm volatile("ldmatrix.sync.aligned.m8n8.x4.trans.shared.b16 {%0,%1,%2,%3},[%4];"
                 : "=r"(r0), "=r"(r1), "=r"(r2), "=r"(r3) : "r"(addr));
}
__device__ __forceinline__ void mma16816(float* cc, const unsigned* aa, const unsigned* bb) {
    asm volatile("mma.sync.aligned.m16n8k16.row.col.f32.f16.f16.f32 "
                 "{%0,%1,%2,%3},{%4,%5,%6,%7},{%8,%9},{%0,%1,%2,%3};"
                 : "+f"(cc[0]), "+f"(cc[1]), "+f"(cc[2]), "+f"(cc[3])
                 : "r"(aa[0]), "r"(aa[1]), "r"(aa[2]), "r"(aa[3]), "r"(bb[0]), "r"(bb[1]));
}
__device__ __forceinline__ unsigned pack2(float a, float b) {
    __half2 h = __floats2half2_rn(a, b);
    return *reinterpret_cast<unsigned*>(&h);
}
__device__ __forceinline__ void cpa16(void* dst, const void* src) {
    asm volatile("cp.async.cg.shared.global [%0], [%1], 16;"
                 :: "r"(sptr(dst)), "l"(src));
}
__device__ __forceinline__ void cpcommit() {
    asm volatile("cp.async.commit_group;");
}
template<int N> __device__ __forceinline__ void cpwait() {
    asm volatile("cp.async.wait_group %0;" :: "n"(N));
}

// ---------- 256-thread tile GEMM, B via packed coalesced LDG ----------
__device__ __forceinline__ void mma_tile_pk(const __half* Amat, const uint4* __restrict__ pw,
                                            float acc[4][4][4]) {
    const int lane = threadIdx.x & 31;
    const int warp = threadIdx.x >> 5;
    const int wy = warp >> 2;
    const int wx = warp & 3;
    const int r16 = lane & 15;
    const int hi8 = (lane >> 4) * 8;
    const uint4* pbase = pw + wx * 512 + lane * 2;   // uint4 units
    #pragma unroll
    for (int k0s = 0; k0s < 8; ++k0s) {
        unsigned afrag[4][4];
        #pragma unroll
        for (int i = 0; i < 4; ++i) {
            unsigned addr = sptr(Amat + (wy * 64 + i * 16 + r16) * HP + k0s * 16 + hi8);
            ldsm4(afrag[i][0], afrag[i][1], afrag[i][2], afrag[i][3], addr);
        }
        uint4 u0 = pbase[k0s * 64];
        uint4 u1 = pbase[k0s * 64 + 1];
        unsigned bfrag[4][2];
        bfrag[0][0] = u0.x; bfrag[0][1] = u0.y;
        bfrag[1][0] = u0.z; bfrag[1][1] = u0.w;
        bfrag[2][0] = u1.x; bfrag[2][1] = u1.y;
        bfrag[3][0] = u1.z; bfrag[3][1] = u1.w;
        #pragma unroll
        for (int i = 0; i < 4; ++i)
            #pragma unroll
            for (int j = 0; j < 4; ++j)
                mma16816(acc[i][j], afrag[i], bfrag[j]);
    }
}

// writeback accumulators (+bias, optional relu) into an f16 smem tile [128][HP]
__device__ __forceinline__ void store_tile(__half* dst, float acc[4][4][4],
                                           const float* __restrict__ bias, bool doRelu) {
    const int lane = threadIdx.x & 31;
    const int warp = threadIdx.x >> 5;
    const int wy = warp >> 2;
    const int wx = warp & 3;
    const int gid = lane >> 2;
    const int tig = lane & 3;
    #pragma unroll
    for (int i = 0; i < 4; ++i) {
        int row = wy * 64 + i * 16 + gid;
        #pragma unroll
        for (int j = 0; j < 4; ++j) {
            int col = wx * 32 + j * 8 + tig * 2;
            float2 bv = *(const float2*)(bias + col);
            float o0 = acc[i][j][0] + bv.x;
            float o1 = acc[i][j][1] + bv.y;
            float o2 = acc[i][j][2] + bv.x;
            float o3 = acc[i][j][3] + bv.y;
            if (doRelu) {
                o0 = fmaxf(o0, 0.f); o1 = fmaxf(o1, 0.f);
                o2 = fmaxf(o2, 0.f); o3 = fmaxf(o3, 0.f);
            }
            *(__half2*)(dst + row * HP + col)       = __floats2half2_rn(o0, o1);
            *(__half2*)(dst + (row + 8) * HP + col) = __floats2half2_rn(o2, o3);
        }
    }
}

// =====================================================================
// Kernel 0: fp32 -> packed-fragment fp16 conversion for all 6 weights.
// idx decomposition: j = idx&3, lane = (idx>>2)&31, k0s = (idx>>7)&7, wx = idx>>10.
// =====================================================================
__global__ void conv_kernel(const float* __restrict__ Wq, const float* __restrict__ Wkh,
                            const float* __restrict__ Wvh, const float* __restrict__ Wo,
                            const float* __restrict__ Wf1, const float* __restrict__ Wf2)
{
    int idx = blockIdx.x * 256 + threadIdx.x;   // [0, 4096)
    int j    = idx & 3;
    int lane = (idx >> 2) & 31;
    int k0s  = (idx >> 7) & 7;
    int wx   = idx >> 10;
    int gid = lane >> 2;
    int tig = lane & 3;
    int n = wx * 32 + j * 8 + gid;
    int k = k0s * 16 + 2 * tig;

    uint2 e;
    e.x = pack2(Wq[k * 128 + n],       Wq[(k + 1) * 128 + n]);
    e.y = pack2(Wq[(k + 8) * 128 + n], Wq[(k + 9) * 128 + n]);
    g_pq[idx] = e;
    e.x = pack2(Wkh[k * 128 + n],       Wkh[(k + 1) * 128 + n]);
    e.y = pack2(Wkh[(k + 8) * 128 + n], Wkh[(k + 9) * 128 + n]);
    g_pkh[idx] = e;
    e.x = pack2(Wvh[k * 128 + n],       Wvh[(k + 1) * 128 + n]);
    e.y = pack2(Wvh[(k + 8) * 128 + n], Wvh[(k + 9) * 128 + n]);
    g_pvh[idx] = e;
    e.x = pack2(Wo[k * 128 + n],       Wo[(k + 1) * 128 + n]);
    e.y = pack2(Wo[(k + 8) * 128 + n], Wo[(k + 9) * 128 + n]);
    g_po[idx] = e;
    e.x = pack2(Wf1[k * 128 + n],       Wf1[(k + 1) * 128 + n]);
    e.y = pack2(Wf1[(k + 8) * 128 + n], Wf1[(k + 9) * 128 + n]);
    g_pf1[idx] = e;
    e.x = pack2(Wf2[k * 128 + n],       Wf2[(k + 1) * 128 + n]);
    e.y = pack2(Wf2[(k + 8) * 128 + n], Wf2[(k + 9) * 128 + n]);
    g_pf2[idx] = e;
}

// =====================================================================
// Attention warp body (unchanged from R11).
// =====================================================================
template<int NP>
__device__ __forceinline__ void attn_warp(const __half* Qs, const __half* Ks, const __half* Vs,
                                          int base, int w, int lane)
{
    const int r16 = lane & 15;
    const int hi8 = (lane >> 4) * 8;
    const int gid = lane >> 2;
    const int tig = lane & 3;

    unsigned aq[8][4];
    #pragma unroll
    for (int k = 0; k < 8; ++k) {
        unsigned addr = sptr(Qs + (16 * w + r16) * HP + k * 16 + hi8);
        ldsm4(aq[k][0], aq[k][1], aq[k][2], aq[k][3], addr);
    }

    float c[2 * NP][4];
    #pragma unroll
    for (int js = 0; js < 2 * NP; ++js) {
        c[js][0] = 0.f; c[js][1] = 0.f; c[js][2] = 0.f; c[js][3] = 0.f;
    }
    #pragma unroll
    for (int jp = 0; jp < NP; ++jp) {
        #pragma unroll
        for (int k = 0; k < 8; ++k) {
            unsigned t0, t1, t2, t3;
            unsigned addr = sptr(Ks + (16 * jp + r16) * HP + k * 16 + hi8);
            ldsm4(t0, t1, t2, t3, addr);
            unsigned bE[2] = { t0, t2 };
            unsigned bO[2] = { t1, t3 };
            mma16816(c[2 * jp],     aq[k], bE);
            mma16816(c[2 * jp + 1], aq[k], bO);
        }
    }

    const float scale = 0.08838834764831845f;   // 1/sqrt(128)
    const int tlo = 16 * w + gid;
    const int thi = tlo + 8;
    float mlo = -1e30f, mhi = -1e30f;
    #pragma unroll
    for (int js = 0; js < 2 * NP; ++js) {
        int s0 = 8 * js + 2 * tig;
        int s1 = s0 + 1;
        c[js][0] *= scale; c[js][1] *= scale;
        c[js][2] *= scale; c[js][3] *= scale;
        if (js >= 2 * NP - 2) {          // diagonal block: causal mask
            if (s0 > tlo) c[js][0] = -1e30f;
            if (s1 > tlo) c[js][1] = -1e30f;
            if (s0 > thi) c[js][2] = -1e30f;
            if (s1 > thi) c[js][3] = -1e30f;
        }
        mlo = fmaxf(mlo, fmaxf(c[js][0], c[js][1]));
        mhi = fmaxf(mhi, fmaxf(c[js][2], c[js][3]));
    }
    #pragma unroll
    for (int o = 1; o <= 2; o <<= 1) {
        mlo = fmaxf(mlo, __shfl_xor_sync(0xffffffffu, mlo, o));
        mhi = fmaxf(mhi, __shfl_xor_sync(0xffffffffu, mhi, o));
    }
    float slo = 0.f, shi = 0.f;
    #pragma unroll
    for (int js = 0; js < 2 * NP; ++js) {
        c[js][0] = __expf(c[js][0] - mlo);
        c[js][1] = __expf(c[js][1] - mlo);
        c[js][2] = __expf(c[js][2] - mhi);
        c[js][3] = __expf(c[js][3] - mhi);
        slo += c[js][0] + c[js][1];
        shi += c[js][2] + c[js][3];
    }
    #pragma unroll
    for (int o = 1; o <= 2; o <<= 1) {
        slo += __shfl_xor_sync(0xffffffffu, slo, o);
        shi += __shfl_xor_sync(0xffffffffu, shi, o);
    }
    const float invlo = 1.f / slo;
    const float invhi = 1.f / shi;

    float ov[16][4];
    #pragma unroll
    for (int jt = 0; jt < 16; ++jt) {
        ov[jt][0] = 0.f; ov[jt][1] = 0.f; ov[jt][2] = 0.f; ov[jt][3] = 0.f;
    }
    #pragma unroll
    for (int ks = 0; ks < NP; ++ks) {
        unsigned ap[4];
        ap[0] = pack2(c[2 * ks][0],     c[2 * ks][1]);
        ap[1] = pack2(c[2 * ks][2],     c[2 * ks][3]);
        ap[2] = pack2(c[2 * ks + 1][0], c[2 * ks + 1][1]);
        ap[3] = pack2(c[2 * ks + 1][2], c[2 * ks + 1][3]);
        #pragma unroll
        for (int jf = 0; jf < 8; ++jf) {
            unsigned t0, t1, t2, t3;
            unsigned addr = sptr(Vs + (16 * ks + r16) * HP + jf * 16 + hi8);
            ldsm4t(t0, t1, t2, t3, addr);
            unsigned b0[2] = { t0, t1 };
            unsigned b1[2] = { t2, t3 };
            mma16816(ov[2 * jf],     ap, b0);
            mma16816(ov[2 * jf + 1], ap, b1);
        }
    }

    __half* olo = g_attn + (base + tlo * NN) * FF;
    __half* ohi = g_attn + (base + thi * NN) * FF;
    #pragma unroll
    for (int jt = 0; jt < 16; ++jt) {
        int col = jt * 8 + tig * 2;
        *(__half2*)(olo + col) = __floats2half2_rn(ov[jt][0] * invlo, ov[jt][1] * invlo);
        *(__half2*)(ohi + col) = __floats2half2_rn(ov[jt][2] * invhi, ov[jt][3] * invhi);
    }
}

// =====================================================================
// Kernel 1 (fused qkv + attention), 256 threads, 2 CTAs/SM.
// 3 smem buffers; weights via packed coalesced LDG.
// =====================================================================
__global__ __launch_bounds__(256, 2) void fused_attn_kernel(
    const float* __restrict__ xl, const float* __restrict__ xh,
    const float* __restrict__ te,
    const float* __restrict__ bq, const float* __restrict__ bkh,
    const float* __restrict__ bvh)
{
    extern __shared__ char smraw[];
    __half* X1 = (__half*)smraw;          // xh+te -> later K
    __half* X2 = X1 + 128 * HP;           // xl+te -> later Q
    __half* C  = X2 + 128 * HP;           // V

    const int head = blockIdx.x;
    const int bidx = head >> 8;
    const int nidx = head & 255;
    const int base = bidx * TT * NN + nidx;

    const int tid = threadIdx.x;
    const int w = tid >> 5;
    const int lane = tid & 31;

    const float4* xl4 = (const float4*)xl;
    const float4* xh4 = (const float4*)xh;
    const float4* te4 = (const float4*)te;

    #pragma unroll
    for (int v = tid; v < 4096; v += 256) {
        int row = v >> 5;
        int c4 = v & 31;
        float4 tval = te4[(bidx * TT + row) * 32 + c4];
        float4 ah = xh4[(base + row * NN) * 32 + c4];
        __half2* dh = (__half2*)(X1 + row * HP + c4 * 4);
        dh[0] = __floats2half2_rn(ah.x + tval.x, ah.y + tval.y);
        dh[1] = __floats2half2_rn(ah.z + tval.z, ah.w + tval.w);
        float4 al = xl4[(base + row * NN) * 32 + c4];
        __half2* dl = (__half2*)(X2 + row * HP + c4 * 4);
        dl[0] = __floats2half2_rn(al.x + tval.x, al.y + tval.y);
        dl[1] = __floats2half2_rn(al.z + tval.z, al.w + tval.w);
    }
    __syncthreads();

    {
        float accV[4][4][4] = {};
        mma_tile_pk(X1, (const uint4*)g_pvh, accV);
        store_tile(C, accV, bvh, true);
    }
    {
        float accK[4][4][4] = {};
        mma_tile_pk(X1, (const uint4*)g_pkh, accK);
        __syncthreads();                 // all X1 reads done
        store_tile(X1, accK, bkh, true); // K -> X1
    }
    {
        float accQ[4][4][4] = {};
        mma_tile_pk(X2, (const uint4*)g_pq, accQ);
        __syncthreads();                 // all X2 reads done; K store visible
        store_tile(X2, accQ, bq, false); // Q -> X2
    }
    __syncthreads();                     // Q/K/V visible

    switch (w) {
        case 0: attn_warp<1>(X2, X1, C, base, 0, lane); break;
        case 1: attn_warp<2>(X2, X1, C, base, 1, lane); break;
        case 2: attn_warp<3>(X2, X1, C, base, 2, lane); break;
        case 3: attn_warp<4>(X2, X1, C, base, 3, lane); break;
        case 4: attn_warp<5>(X2, X1, C, base, 4, lane); break;
        case 5: attn_warp<6>(X2, X1, C, base, 5, lane); break;
        case 6: attn_warp<7>(X2, X1, C, base, 6, lane); break;
        default: attn_warp<8>(X2, X1, C, base, 7, lane); break;
    }
}

// =====================================================================
// Kernel 2 (fused proj+ffn), 256 threads, 2 CTAs/SM.
// Weights via packed coalesced LDG; only attn tile staged.
// =====================================================================
__global__ __launch_bounds__(256, 2) void tail_kernel(
    float* __restrict__ outp,
    const float* __restrict__ xl, const float* __restrict__ te,
    const float* __restrict__ bo, const float* __restrict__ bf1,
    const float* __restrict__ bf2)
{
    extern __shared__ char smraw[];
    __half* A1 = (__half*)smraw;          // attn -> ln1 (f16)
    __half* A2 = A1 + 128 * HP;           // h
    float* red1 = (float*)(A2 + 128 * HP);   // [128][4] sums
    float* red2 = red1 + 512;                // [128][4] sumsq

    const int m0 = blockIdx.x * 128;
    const int tid = threadIdx.x;
    const float* teRow = te + (m0 / NN) * FF;

    #pragma unroll
    for (int v = tid; v < 2048; v += 256) {
        int row = v >> 4;
        int q16 = v & 15;
        cpa16(A1 + row * HP + q16 * 8, ((const uint4*)(g_attn + (m0 + row) * FF)) + q16);
    }
    cpcommit();
    cpwait<0>();
    __syncthreads();

    const int lane = tid & 31;
    const int warp = tid >> 5;
    const int wy = warp >> 2;
    const int wx = warp & 3;
    const int gid = lane >> 2;
    const int tig = lane & 3;

    // ---- proj GEMM ----
    float acc[4][4][4] = {};
    mma_tile_pk(A1, (const uint4*)g_po, acc);

    // ---- val = acc + bo + xl + te ; LN1 partials ----
    #pragma unroll
    for (int i = 0; i < 4; ++i) {
        int rlo = wy * 64 + i * 16 + gid;
        int rhi = rlo + 8;
        float s1lo = 0.f, s2lo = 0.f, s1hi = 0.f, s2hi = 0.f;
        #pragma unroll
        for (int j = 0; j < 4; ++j) {
            int col = wx * 32 + j * 8 + tig * 2;
            float2 bv = *(const float2*)(bo + col);
            float2 x0 = *(const float2*)(xl + (m0 + rlo) * FF + col);
            float2 x1 = *(const float2*)(xl + (m0 + rhi) * FF + col);
            float2 t0 = *(const float2*)(teRow + col);
            float v0 = acc[i][j][0] + bv.x + x0.x + t0.x;
            float v1 = acc[i][j][1] + bv.y + x0.y + t0.y;
            float v2 = acc[i][j][2] + bv.x + x1.x + t0.x;
            float v3 = acc[i][j][3] + bv.y + x1.y + t0.y;
            acc[i][j][0] = v0; acc[i][j][1] = v1;
            acc[i][j][2] = v2; acc[i][j][3] = v3;
            s1lo += v0 + v1; s2lo += v0 * v0 + v1 * v1;
            s1hi += v2 + v3; s2hi += v2 * v2 + v3 * v3;
        }
        #pragma unroll
        for (int o = 1; o <= 2; o <<= 1) {
            s1lo += __shfl_xor_sync(0xffffffffu, s1lo, o);
            s2lo += __shfl_xor_sync(0xffffffffu, s2lo, o);
            s1hi += __shfl_xor_sync(0xffffffffu, s1hi, o);
            s2hi += __shfl_xor_sync(0xffffffffu, s2hi, o);
        }
        if (tig == 0) {
            red1[rlo * 4 + wx] = s1lo; red2[rlo * 4 + wx] = s2lo;
            red1[rhi * 4 + wx] = s1hi; red2[rhi * 4 + wx] = s2hi;
        }
    }
    __syncthreads();   // A1 reads done + red visible

    // ---- LN1 finalize -> ln1 (f16) into A1 ----
    #pragma unroll
    for (int i = 0; i < 4; ++i) {
        int rlo = wy * 64 + i * 16 + gid;
        int rhi = rlo + 8;
        float mlo = (red1[rlo * 4] + red1[rlo * 4 + 1] + red1[rlo * 4 + 2] + red1[rlo * 4 + 3]) * 0.0078125f;
        float vlo = (red2[rlo * 4] + red2[rlo * 4 + 1] + red2[rlo * 4 + 2] + red2[rlo * 4 + 3]) * 0.0078125f - mlo * mlo;
        float rslo = rsqrtf(vlo + 1e-5f);
        float mhi = (red1[rhi * 4] + red1[rhi * 4 + 1] + red1[rhi * 4 + 2] + red1[rhi * 4 + 3]) * 0.0078125f;
        float vhi = (red2[rhi * 4] + red2[rhi * 4 + 1] + red2[rhi * 4 + 2] + red2[rhi * 4 + 3]) * 0.0078125f - mhi * mhi;
        float rshi = rsqrtf(vhi + 1e-5f);
        #pragma unroll
        for (int j = 0; j < 4; ++j) {
            int col = wx * 32 + j * 8 + tig * 2;
            *(__half2*)(A1 + rlo * HP + col) =
                __floats2half2_rn((acc[i][j][0] - mlo) * rslo, (acc[i][j][1] - mlo) * rslo);
            *(__half2*)(A1 + rhi * HP + col) =
                __floats2half2_rn((acc[i][j][2] - mhi) * rshi, (acc[i][j][3] - mhi) * rshi);
        }
    }
    __syncthreads();   // ln1 visible

    // ---- FFN GEMM 1: h = relu(ln1 @ Wf1 + bf1) -> A2 ----
    float acc2[4][4][4] = {};
    mma_tile_pk(A1, (const uint4*)g_pf1, acc2);
    store_tile(A2, acc2, bf1, true);
    __syncthreads();   // h visible

    // ---- FFN GEMM 2 ----
    float acc3[4][4][4] = {};
    mma_tile_pk(A2, (const uint4*)g_pf2, acc3);

    // ---- acc3 += bf2 + ln1(A1); LN2 partials ----
    #pragma unroll
    for (int i = 0; i < 4; ++i) {
        int rlo = wy * 64 + i * 16 + gid;
        int rhi = rlo + 8;
        float s1lo = 0.f, s2lo = 0.f, s1hi = 0.f, s2hi = 0.f;
        #pragma unroll
        for (int j = 0; j < 4; ++j) {
            int col = wx * 32 + j * 8 + tig * 2;
            float2 bv = *(const float2*)(bf2 + col);
            float2 l0 = __half22float2(*(const __half2*)(A1 + rlo * HP + col));
            float2 l1 = __half22float2(*(const __half2*)(A1 + rhi * HP + col));
            float v0 = acc3[i][j][0] + bv.x + l0.x;
            float v1 = acc3[i][j][1] + bv.y + l0.y;
            float v2 = acc3[i][j][2] + bv.x + l1.x;
            float v3 = acc3[i][j][3] + bv.y + l1.y;
            acc3[i][j][0] = v0; acc3[i][j][1] = v1;
            acc3[i][j][2] = v2; acc3[i][j][3] = v3;
            s1lo += v0 + v1; s2lo += v0 * v0 + v1 * v1;
            s1hi += v2 + v3; s2hi += v2 * v2 + v3 * v3;
        }
        #pragma unroll
        for (int o = 1; o <= 2; o <<= 1) {
            s1lo += __shfl_xor_sync(0xffffffffu, s1lo, o);
            s2lo += __shfl_xor_sync(0xffffffffu, s2lo, o);
            s1hi += __shfl_xor_sync(0xffffffffu, s1hi, o);
            s2hi += __shfl_xor_sync(0xffffffffu, s2hi, o);
        }
        if (tig == 0) {
            red1[rlo * 4 + wx] = s1lo; red2[rlo * 4 + wx] = s2lo;
            red1[rhi * 4 + wx] = s1hi; red2[rhi * 4 + wx] = s2hi;
        }
    }
    __syncthreads();

    // ---- LN2 finalize -> output ----
    #pragma unroll
    for (int i = 0; i < 4; ++i) {
        int rlo = wy * 64 + i * 16 + gid;
        int rhi = rlo + 8;
        float mlo = (red1[rlo * 4] + red1[rlo * 4 + 1] + red1[rlo * 4 + 2] + red1[rlo * 4 + 3]) * 0.0078125f;
        float vlo = (red2[rlo * 4] + red2[rlo * 4 + 1] + red2[rlo * 4 + 2] + red2[rlo * 4 + 3]) * 0.0078125f - mlo * mlo;
        float rslo = rsqrtf(vlo + 1e-5f);
        float mhi = (red1[rhi * 4] + red1[rhi * 4 + 1] + red1[rhi * 4 + 2] + red1[rhi * 4 + 3]) * 0.0078125f;
        float vhi = (red2[rhi * 4] + red2[rhi * 4 + 1] + red2[rhi * 4 + 2] + red2[rhi * 4 + 3]) * 0.0078125f - mhi * mhi;
        float rshi = rsqrtf(vhi + 1e-5f);
        #pragma unroll
        for (int j = 0; j < 4; ++j) {
            int col = wx * 32 + j * 8 + tig * 2;
            float2 o0, o1;
            o0.x = (acc3[i][j][0] - mlo) * rslo;
            o0.y = (acc3[i][j][1] - mlo) * rslo;
            o1.x = (acc3[i][j][2] - mhi) * rshi;
            o1.y = (acc3[i][j][3] - mhi) * rshi;
            *(float2*)(outp + (m0 + rlo) * FF + col) = o0;
            *(float2*)(outp + (m0 + rhi) * FF + col) = o1;
        }
    }
}

// =====================================================================
extern "C" void kernel_launch(void* const* d_in, const int* in_sizes, int n_in,
                              void* d_out, int out_size)
{
    const float* xl  = (const float*)d_in[0];
    const float* xh  = (const float*)d_in[1];
    const float* te  = (const float*)d_in[2];
    const float* Wq  = (const float*)d_in[3];
    const float* bq  = (const float*)d_in[4];
    const float* Wkh = (const float*)d_in[5];
    const float* bkh = (const float*)d_in[6];
    const float* Wvh = (const float*)d_in[7];
    const float* bvh = (const float*)d_in[8];
    const float* Wo  = (const float*)d_in[9];
    const float* bo  = (const float*)d_in[10];
    const float* Wf1 = (const float*)d_in[11];
    const float* bf1 = (const float*)d_in[12];
    const float* Wf2 = (const float*)d_in[13];
    const float* bf2 = (const float*)d_in[14];
    float* outp = (float*)d_out;

    const int smFused = 3 * 128 * HP * 2;                     // 104448
    const int smTail  = 2 * 128 * HP * 2 + 4096;              // 73728

    cudaFuncSetAttribute(fused_attn_kernel, cudaFuncAttributeMaxDynamicSharedMemorySize, smFused);
    cudaFuncSetAttribute(tail_kernel,       cudaFuncAttributeMaxDynamicSharedMemorySize, smTail);

    conv_kernel<<<16, 256>>>(Wq, Wkh, Wvh, Wo, Wf1, Wf2);
    fused_attn_kernel<<<BB * NN, 256, smFused>>>(xl, xh, te, bq, bkh, bvh);
    tail_kernel<<<MTOT / 128, 256, smTail>>>(outp, xl, te, bo, bf1, bf2);
}

// round 14
// speedup vs baseline: 1.3771x; 1.0860x over previous
#include <cuda_runtime.h>
#include <cuda_fp16.h>
#include <math.h>

constexpr int BB = 8;
constexpr int TT = 128;
constexpr int NN = 256;
constexpr int FF = 128;
constexpr int MTOT = BB * TT * NN;   // 262144
constexpr int HP = 136;              // smem half pitch (padded)

// packed fragment-order weights: [wx][k0step][lane][j] -> uint2 {b0, b1}
__device__ __align__(16) uint2 g_pq [4096];
__device__ __align__(16) uint2 g_pkh[4096];
__device__ __align__(16) uint2 g_pvh[4096];
__device__ __align__(16) uint2 g_po [4096];
__device__ __align__(16) uint2 g_pf1[4096];
__device__ __align__(16) uint2 g_pf2[4096];

// ------------------- asm helpers -------------------
__device__ __forceinline__ unsigned sptr(const void* ptr) {
    return (unsigned)__cvta_generic_to_shared(ptr);
}
__device__ __forceinline__ void ldsm4(unsigned& r0, unsigned& r1, unsigned& r2, unsigned& r3, unsigned addr) {
    asm volatile("ldmatrix.sync.aligned.m8n8.x4.shared.b16 {%0,%1,%2,%3},[%4];"
                 : "=r"(r0), "=r"(r1), "=r"(r2), "=r"(r3) : "r"(addr));
}
__device__ __forceinline__ void ldsm4t(unsigned& r0, unsigned& r1, unsigned& r2, unsigned& r3, unsigned addr) {
    asm volatile("ldmatrix.sync.aligned.m8n8.x4.trans.shared.b16 {%0,%1,%2,%3},[%4];"
                 : "=r"(r0), "=r"(r1), "=r"(r2), "=r"(r3) : "r"(addr));
}
__device__ __forceinline__ void mma16816(float* cc, const unsigned* aa, const unsigned* bb) {
    asm volatile("mma.sync.aligned.m16n8k16.row.col.f32.f16.f16.f32 "
                 "{%0,%1,%2,%3},{%4,%5,%6,%7},{%8,%9},{%0,%1,%2,%3};"
                 : "+f"(cc[0]), "+f"(cc[1]), "+f"(cc[2]), "+f"(cc[3])
                 : "r"(aa[0]), "r"(aa[1]), "r"(aa[2]), "r"(aa[3]), "r"(bb[0]), "r"(bb[1]));
}
__device__ __forceinline__ unsigned pack2(float a, float b) {
    __half2 h = __floats2half2_rn(a, b);
    return *reinterpret_cast<unsigned*>(&h);
}

// ---------- 256-thread tile GEMM, B via packed coalesced LDG ----------
__device__ __forceinline__ void mma_tile_pk(const __half* Amat, const uint4* __restrict__ pw,
                                            float acc[4][4][4]) {
    const int lane = threadIdx.x & 31;
    const int warp = threadIdx.x >> 5;
    const int wy = warp >> 2;
    const int wx = warp & 3;
    const int r16 = lane & 15;
    const int hi8 = (lane >> 4) * 8;
    const uint4* pbase = pw + wx * 512 + lane * 2;   // uint4 units
    #pragma unroll
    for (int k0s = 0; k0s < 8; ++k0s) {
        unsigned afrag[4][4];
        #pragma unroll
        for (int i = 0; i < 4; ++i) {
            unsigned addr = sptr(Amat + (wy * 64 + i * 16 + r16) * HP + k0s * 16 + hi8);
            ldsm4(afrag[i][0], afrag[i][1], afrag[i][2], afrag[i][3], addr);
        }
        uint4 u0 = pbase[k0s * 64];
        uint4 u1 = pbase[k0s * 64 + 1];
        unsigned bfrag[4][2];
        bfrag[0][0] = u0.x; bfrag[0][1] = u0.y;
        bfrag[1][0] = u0.z; bfrag[1][1] = u0.w;
        bfrag[2][0] = u1.x; bfrag[2][1] = u1.y;
        bfrag[3][0] = u1.z; bfrag[3][1] = u1.w;
        #pragma unroll
        for (int i = 0; i < 4; ++i)
            #pragma unroll
            for (int j = 0; j < 4; ++j)
                mma16816(acc[i][j], afrag[i], bfrag[j]);
    }
}

// writeback accumulators (+bias, optional relu) into an f16 smem tile [128][HP]
__device__ __forceinline__ void store_tile(__half* dst, float acc[4][4][4],
                                           const float* __restrict__ bias, bool doRelu) {
    const int lane = threadIdx.x & 31;
    const int warp = threadIdx.x >> 5;
    const int wy = warp >> 2;
    const int wx = warp & 3;
    const int gid = lane >> 2;
    const int tig = lane & 3;
    #pragma unroll
    for (int i = 0; i < 4; ++i) {
        int row = wy * 64 + i * 16 + gid;
        #pragma unroll
        for (int j = 0; j < 4; ++j) {
            int col = wx * 32 + j * 8 + tig * 2;
            float2 bv = *(const float2*)(bias + col);
            float o0 = acc[i][j][0] + bv.x;
            float o1 = acc[i][j][1] + bv.y;
            float o2 = acc[i][j][2] + bv.x;
            float o3 = acc[i][j][3] + bv.y;
            if (doRelu) {
                o0 = fmaxf(o0, 0.f); o1 = fmaxf(o1, 0.f);
                o2 = fmaxf(o2, 0.f); o3 = fmaxf(o3, 0.f);
            }
            *(__half2*)(dst + row * HP + col)       = __floats2half2_rn(o0, o1);
            *(__half2*)(dst + (row + 8) * HP + col) = __floats2half2_rn(o2, o3);
        }
    }
}

// =====================================================================
// Kernel 0: fp32 -> packed-fragment fp16 conversion for all 6 weights.
// =====================================================================
__global__ void conv_kernel(const float* __restrict__ Wq, const float* __restrict__ Wkh,
                            const float* __restrict__ Wvh, const float* __restrict__ Wo,
                            const float* __restrict__ Wf1, const float* __restrict__ Wf2)
{
    int idx = blockIdx.x * 256 + threadIdx.x;   // [0, 4096)
    int j    = idx & 3;
    int lane = (idx >> 2) & 31;
    int k0s  = (idx >> 7) & 7;
    int wx   = idx >> 10;
    int gid = lane >> 2;
    int tig = lane & 3;
    int n = wx * 32 + j * 8 + gid;
    int k = k0s * 16 + 2 * tig;

    uint2 e;
    e.x = pack2(Wq[k * 128 + n],       Wq[(k + 1) * 128 + n]);
    e.y = pack2(Wq[(k + 8) * 128 + n], Wq[(k + 9) * 128 + n]);
    g_pq[idx] = e;
    e.x = pack2(Wkh[k * 128 + n],       Wkh[(k + 1) * 128 + n]);
    e.y = pack2(Wkh[(k + 8) * 128 + n], Wkh[(k + 9) * 128 + n]);
    g_pkh[idx] = e;
    e.x = pack2(Wvh[k * 128 + n],       Wvh[(k + 1) * 128 + n]);
    e.y = pack2(Wvh[(k + 8) * 128 + n], Wvh[(k + 9) * 128 + n]);
    g_pvh[idx] = e;
    e.x = pack2(Wo[k * 128 + n],       Wo[(k + 1) * 128 + n]);
    e.y = pack2(Wo[(k + 8) * 128 + n], Wo[(k + 9) * 128 + n]);
    g_po[idx] = e;
    e.x = pack2(Wf1[k * 128 + n],       Wf1[(k + 1) * 128 + n]);
    e.y = pack2(Wf1[(k + 8) * 128 + n], Wf1[(k + 9) * 128 + n]);
    g_pf1[idx] = e;
    e.x = pack2(Wf2[k * 128 + n],       Wf2[(k + 1) * 128 + n]);
    e.y = pack2(Wf2[(k + 8) * 128 + n], Wf2[(k + 9) * 128 + n]);
    g_pf2[idx] = e;
}

// =====================================================================
// Attention warp body: results returned in registers (store done by caller
// outside the divergent switch, so block barriers stay uniform).
// =====================================================================
template<int NP>
__device__ __forceinline__ void attn_warp_reg(const __half* Qs, const __half* Ks, const __half* Vs,
                                              int w, int lane,
                                              float ov[16][4], float& invlo, float& invhi)
{
    const int r16 = lane & 15;
    const int hi8 = (lane >> 4) * 8;
    const int gid = lane >> 2;
    const int tig = lane & 3;

    unsigned aq[8][4];
    #pragma unroll
    for (int k = 0; k < 8; ++k) {
        unsigned addr = sptr(Qs + (16 * w + r16) * HP + k * 16 + hi8);
        ldsm4(aq[k][0], aq[k][1], aq[k][2], aq[k][3], addr);
    }

    float c[2 * NP][4];
    #pragma unroll
    for (int js = 0; js < 2 * NP; ++js) {
        c[js][0] = 0.f; c[js][1] = 0.f; c[js][2] = 0.f; c[js][3] = 0.f;
    }
    #pragma unroll
    for (int jp = 0; jp < NP; ++jp) {
        #pragma unroll
        for (int k = 0; k < 8; ++k) {
            unsigned t0, t1, t2, t3;
            unsigned addr = sptr(Ks + (16 * jp + r16) * HP + k * 16 + hi8);
            ldsm4(t0, t1, t2, t3, addr);
            unsigned bE[2] = { t0, t2 };
            unsigned bO[2] = { t1, t3 };
            mma16816(c[2 * jp],     aq[k], bE);
            mma16816(c[2 * jp + 1], aq[k], bO);
        }
    }

    const float scale = 0.08838834764831845f;   // 1/sqrt(128)
    const int tlo = 16 * w + gid;
    const int thi = tlo + 8;
    float mlo = -1e30f, mhi = -1e30f;
    #pragma unroll
    for (int js = 0; js < 2 * NP; ++js) {
        int s0 = 8 * js + 2 * tig;
        int s1 = s0 + 1;
        c[js][0] *= scale; c[js][1] *= scale;
        c[js][2] *= scale; c[js][3] *= scale;
        if (js >= 2 * NP - 2) {          // diagonal block: causal mask
            if (s0 > tlo) c[js][0] = -1e30f;
            if (s1 > tlo) c[js][1] = -1e30f;
            if (s0 > thi) c[js][2] = -1e30f;
            if (s1 > thi) c[js][3] = -1e30f;
        }
        mlo = fmaxf(mlo, fmaxf(c[js][0], c[js][1]));
        mhi = fmaxf(mhi, fmaxf(c[js][2], c[js][3]));
    }
    #pragma unroll
    for (int o = 1; o <= 2; o <<= 1) {
        mlo = fmaxf(mlo, __shfl_xor_sync(0xffffffffu, mlo, o));
        mhi = fmaxf(mhi, __shfl_xor_sync(0xffffffffu, mhi, o));
    }
    float slo = 0.f, shi = 0.f;
    #pragma unroll
    for (int js = 0; js < 2 * NP; ++js) {
        c[js][0] = __expf(c[js][0] - mlo);
        c[js][1] = __expf(c[js][1] - mlo);
        c[js][2] = __expf(c[js][2] - mhi);
        c[js][3] = __expf(c[js][3] - mhi);
        slo += c[js][0] + c[js][1];
        shi += c[js][2] + c[js][3];
    }
    #pragma unroll
    for (int o = 1; o <= 2; o <<= 1) {
        slo += __shfl_xor_sync(0xffffffffu, slo, o);
        shi += __shfl_xor_sync(0xffffffffu, shi, o);
    }
    invlo = 1.f / slo;
    invhi = 1.f / shi;

    #pragma unroll
    for (int jt = 0; jt < 16; ++jt) {
        ov[jt][0] = 0.f; ov[jt][1] = 0.f; ov[jt][2] = 0.f; ov[jt][3] = 0.f;
    }
    #pragma unroll
    for (int ks = 0; ks < NP; ++ks) {
        unsigned ap[4];
        ap[0] = pack2(c[2 * ks][0],     c[2 * ks][1]);
        ap[1] = pack2(c[2 * ks][2],     c[2 * ks][3]);
        ap[2] = pack2(c[2 * ks + 1][0], c[2 * ks + 1][1]);
        ap[3] = pack2(c[2 * ks + 1][2], c[2 * ks + 1][3]);
        #pragma unroll
        for (int jf = 0; jf < 8; ++jf) {
            unsigned t0, t1, t2, t3;
            unsigned addr = sptr(Vs + (16 * ks + r16) * HP + jf * 16 + hi8);
            ldsm4t(t0, t1, t2, t3, addr);
            unsigned b0[2] = { t0, t1 };
            unsigned b1[2] = { t2, t3 };
            mma16816(ov[2 * jf],     ap, b0);
            mma16816(ov[2 * jf + 1], ap, b1);
        }
    }
}

// =====================================================================
// Mega kernel: qkv + causal attention + proj + LN1 + FFN + LN2,
// one head (b,n) per CTA, 256 threads, 2 CTAs/SM.
// Buffers: X1 = xh+te -> K -> attn/ln-? ; X2 = xl+te -> Q -> ln1 ; C = V -> h.
// =====================================================================
__global__ __launch_bounds__(256, 2) void mega_kernel(
    float* __restrict__ outp,
    const float* __restrict__ xl, const float* __restrict__ xh,
    const float* __restrict__ te,
    const float* __restrict__ bq, const float* __restrict__ bkh,
    const float* __restrict__ bvh, const float* __restrict__ bo,
    const float* __restrict__ bf1, const float* __restrict__ bf2)
{
    extern __shared__ char smraw[];
    __half* X1 = (__half*)smraw;          // xh+te -> K -> attn
    __half* X2 = X1 + 128 * HP;           // xl+te -> Q -> ln1
    __half* C  = X2 + 128 * HP;           // V -> h
    float* red1 = (float*)(C + 128 * HP); // [128][4] sums
    float* red2 = red1 + 512;             // [128][4] sumsq

    const int head = blockIdx.x;
    const int bidx = head >> 8;
    const int nidx = head & 255;
    const int base = bidx * TT * NN + nidx;   // row(t)=base+t*NN

    const int tid = threadIdx.x;
    const int w = tid >> 5;
    const int lane = tid & 31;
    const int wy = w >> 2;
    const int wx = w & 3;
    const int gid = lane >> 2;
    const int tig = lane & 3;

    const float4* xl4 = (const float4*)xl;
    const float4* xh4 = (const float4*)xh;
    const float4* te4 = (const float4*)te;

    // ---- stage X1 = xh+te, X2 = xl+te ----
    #pragma unroll
    for (int v = tid; v < 4096; v += 256) {
        int row = v >> 5;
        int c4 = v & 31;
        float4 tval = te4[(bidx * TT + row) * 32 + c4];
        float4 ah = xh4[(base + row * NN) * 32 + c4];
        __half2* dh = (__half2*)(X1 + row * HP + c4 * 4);
        dh[0] = __floats2half2_rn(ah.x + tval.x, ah.y + tval.y);
        dh[1] = __floats2half2_rn(ah.z + tval.z, ah.w + tval.w);
        float4 al = xl4[(base + row * NN) * 32 + c4];
        __half2* dl = (__half2*)(X2 + row * HP + c4 * 4);
        dl[0] = __floats2half2_rn(al.x + tval.x, al.y + tval.y);
        dl[1] = __floats2half2_rn(al.z + tval.z, al.w + tval.w);
    }
    __syncthreads();

    // ---- V, K, Q GEMMs ----
    {
        float accV[4][4][4] = {};
        mma_tile_pk(X1, (const uint4*)g_pvh, accV);
        store_tile(C, accV, bvh, true);
    }
    {
        float accK[4][4][4] = {};
        mma_tile_pk(X1, (const uint4*)g_pkh, accK);
        __syncthreads();                 // all X1 reads done
        store_tile(X1, accK, bkh, true); // K -> X1
    }
    {
        float accQ[4][4][4] = {};
        mma_tile_pk(X2, (const uint4*)g_pq, accQ);
        __syncthreads();                 // all X2 reads done; K store visible
        store_tile(X2, accQ, bq, false); // Q -> X2
    }
    __syncthreads();                     // Q/K/V visible

    // ---- causal attention: Q=X2, K=X1, V=C ----
    float ov[16][4];
    float invlo, invhi;
    switch (w) {
        case 0: attn_warp_reg<1>(X2, X1, C, 0, lane, ov, invlo, invhi); break;
        case 1: attn_warp_reg<2>(X2, X1, C, 1, lane, ov, invlo, invhi); break;
        case 2: attn_warp_reg<3>(X2, X1, C, 2, lane, ov, invlo, invhi); break;
        case 3: attn_warp_reg<4>(X2, X1, C, 3, lane, ov, invlo, invhi); break;
        case 4: attn_warp_reg<5>(X2, X1, C, 4, lane, ov, invlo, invhi); break;
        case 5: attn_warp_reg<6>(X2, X1, C, 5, lane, ov, invlo, invhi); break;
        case 6: attn_warp_reg<7>(X2, X1, C, 6, lane, ov, invlo, invhi); break;
        default: attn_warp_reg<8>(X2, X1, C, 7, lane, ov, invlo, invhi); break;
    }
    __syncthreads();    // all Q/K/V smem reads done

    // ---- store normalized attn (f16) -> X1 ----
    {
        const int tlo = 16 * w + gid;
        const int thi = tlo + 8;
        #pragma unroll
        for (int jt = 0; jt < 16; ++jt) {
            int col = jt * 8 + tig * 2;
            *(__half2*)(X1 + tlo * HP + col) =
                __floats2half2_rn(ov[jt][0] * invlo, ov[jt][1] * invlo);
            *(__half2*)(X1 + thi * HP + col) =
                __floats2half2_rn(ov[jt][2] * invhi, ov[jt][3] * invhi);
        }
    }
    __syncthreads();    // attn visible

    // ================= tail phase (rows r -> global row base + r*NN) ==========

    // ---- proj GEMM ----
    float acc[4][4][4] = {};
    mma_tile_pk(X1, (const uint4*)g_po, acc);

    // ---- val = acc + bo + xl + te ; LN1 partials ----
    #pragma unroll
    for (int i = 0; i < 4; ++i) {
        int rlo = wy * 64 + i * 16 + gid;
        int rhi = rlo + 8;
        float s1lo = 0.f, s2lo = 0.f, s1hi = 0.f, s2hi = 0.f;
        #pragma unroll
        for (int j = 0; j < 4; ++j) {
            int col = wx * 32 + j * 8 + tig * 2;
            float2 bv = *(const float2*)(bo + col);
            float2 x0 = *(const float2*)(xl + (base + rlo * NN) * FF + col);
            float2 x1 = *(const float2*)(xl + (base + rhi * NN) * FF + col);
            float2 t0 = *(const float2*)(te + (bidx * TT + rlo) * FF + col);
            float2 t1 = *(const float2*)(te + (bidx * TT + rhi) * FF + col);
            float v0 = acc[i][j][0] + bv.x + x0.x + t0.x;
            float v1 = acc[i][j][1] + bv.y + x0.y + t0.y;
            float v2 = acc[i][j][2] + bv.x + x1.x + t1.x;
            float v3 = acc[i][j][3] + bv.y + x1.y + t1.y;
            acc[i][j][0] = v0; acc[i][j][1] = v1;
            acc[i][j][2] = v2; acc[i][j][3] = v3;
            s1lo += v0 + v1; s2lo += v0 * v0 + v1 * v1;
            s1hi += v2 + v3; s2hi += v2 * v2 + v3 * v3;
        }
        #pragma unroll
        for (int o = 1; o <= 2; o <<= 1) {
            s1lo += __shfl_xor_sync(0xffffffffu, s1lo, o);
            s2lo += __shfl_xor_sync(0xffffffffu, s2lo, o);
            s1hi += __shfl_xor_sync(0xffffffffu, s1hi, o);
            s2hi += __shfl_xor_sync(0xffffffffu, s2hi, o);
        }
        if (tig == 0) {
            red1[rlo * 4 + wx] = s1lo; red2[rlo * 4 + wx] = s2lo;
            red1[rhi * 4 + wx] = s1hi; red2[rhi * 4 + wx] = s2hi;
        }
    }
    __syncthreads();   // red visible (X1 reads also done)

    // ---- LN1 finalize -> ln1 (f16) into X2 ----
    #pragma unroll
    for (int i = 0; i < 4; ++i) {
        int rlo = wy * 64 + i * 16 + gid;
        int rhi = rlo + 8;
        float mlo = (red1[rlo * 4] + red1[rlo * 4 + 1] + red1[rlo * 4 + 2] + red1[rlo * 4 + 3]) * 0.0078125f;
        float vlo = (red2[rlo * 4] + red2[rlo * 4 + 1] + red2[rlo * 4 + 2] + red2[rlo * 4 + 3]) * 0.0078125f - mlo * mlo;
        float rslo = rsqrtf(vlo + 1e-5f);
        float mhi = (red1[rhi * 4] + red1[rhi * 4 + 1] + red1[rhi * 4 + 2] + red1[rhi * 4 + 3]) * 0.0078125f;
        float vhi = (red2[rhi * 4] + red2[rhi * 4 + 1] + red2[rhi * 4 + 2] + red2[rhi * 4 + 3]) * 0.0078125f - mhi * mhi;
        float rshi = rsqrtf(vhi + 1e-5f);
        #pragma unroll
        for (int j = 0; j < 4; ++j) {
            int col = wx * 32 + j * 8 + tig * 2;
            *(__half2*)(X2 + rlo * HP + col) =
                __floats2half2_rn((acc[i][j][0] - mlo) * rslo, (acc[i][j][1] - mlo) * rslo);
            *(__half2*)(X2 + rhi * HP + col) =
                __floats2half2_rn((acc[i][j][2] - mhi) * rshi, (acc[i][j][3] - mhi) * rshi);
        }
    }
    __syncthreads();   // ln1 visible

    // ---- FFN GEMM 1: h = relu(ln1 @ Wf1 + bf1) -> C ----
    float acc2[4][4][4] = {};
    mma_tile_pk(X2, (const uint4*)g_pf1, acc2);
    store_tile(C, acc2, bf1, true);
    __syncthreads();   // h visible

    // ---- FFN GEMM 2 ----
    float acc3[4][4][4] = {};
    mma_tile_pk(C, (const uint4*)g_pf2, acc3);

    // ---- acc3 += bf2 + ln1(X2); LN2 partials ----
    #pragma unroll
    for (int i = 0; i < 4; ++i) {
        int rlo = wy * 64 + i * 16 + gid;
        int rhi = rlo + 8;
        float s1lo = 0.f, s2lo = 0.f, s1hi = 0.f, s2hi = 0.f;
        #pragma unroll
        for (int j = 0; j < 4; ++j) {
            int col = wx * 32 + j * 8 + tig * 2;
            float2 bv = *(const float2*)(bf2 + col);
            float2 l0 = __half22float2(*(const __half2*)(X2 + rlo * HP + col));
            float2 l1 = __half22float2(*(const __half2*)(X2 + rhi * HP + col));
            float v0 = acc3[i][j][0] + bv.x + l0.x;
            float v1 = acc3[i][j][1] + bv.y + l0.y;
            float v2 = acc3[i][j][2] + bv.x + l1.x;
            float v3 = acc3[i][j][3] + bv.y + l1.y;
            acc3[i][j][0] = v0; acc3[i][j][1] = v1;
            acc3[i][j][2] = v2; acc3[i][j][3] = v3;
            s1lo += v0 + v1; s2lo += v0 * v0 + v1 * v1;
            s1hi += v2 + v3; s2hi += v2 * v2 + v3 * v3;
        }
        #pragma unroll
        for (int o = 1; o <= 2; o <<= 1) {
            s1lo += __shfl_xor_sync(0xffffffffu, s1lo, o);
            s2lo += __shfl_xor_sync(0xffffffffu, s2lo, o);
            s1hi += __shfl_xor_sync(0xffffffffu, s1hi, o);
            s2hi += __shfl_xor_sync(0xffffffffu, s2hi, o);
        }
        if (tig == 0) {
            red1[rlo * 4 + wx] = s1lo; red2[rlo * 4 + wx] = s2lo;
            red1[rhi * 4 + wx] = s1hi; red2[rhi * 4 + wx] = s2hi;
        }
    }
    __syncthreads();

    // ---- LN2 finalize -> output ----
    #pragma unroll
    for (int i = 0; i < 4; ++i) {
        int rlo = wy * 64 + i * 16 + gid;
        int rhi = rlo + 8;
        float mlo = (red1[rlo * 4] + red1[rlo * 4 + 1] + red1[rlo * 4 + 2] + red1[rlo * 4 + 3]) * 0.0078125f;
        float vlo = (red2[rlo * 4] + red2[rlo * 4 + 1] + red2[rlo * 4 + 2] + red2[rlo * 4 + 3]) * 0.0078125f - mlo * mlo;
        float rslo = rsqrtf(vlo + 1e-5f);
        float mhi = (red1[rhi * 4] + red1[rhi * 4 + 1] + red1[rhi * 4 + 2] + red1[rhi * 4 + 3]) * 0.0078125f;
        float vhi = (red2[rhi * 4] + red2[rhi * 4 + 1] + red2[rhi * 4 + 2] + red2[rhi * 4 + 3]) * 0.0078125f - mhi * mhi;
        float rshi = rsqrtf(vhi + 1e-5f);
        #pragma unroll
        for (int j = 0; j < 4; ++j) {
            int col = wx * 32 + j * 8 + tig * 2;
            float2 o0, o1;
            o0.x = (acc3[i][j][0] - mlo) * rslo;
            o0.y = (acc3[i][j][1] - mlo) * rslo;
            o1.x = (acc3[i][j][2] - mhi) * rshi;
            o1.y = (acc3[i][j][3] - mhi) * rshi;
            *(float2*)(outp + (base + rlo * NN) * FF + col) = o0;
            *(float2*)(outp + (base + rhi * NN) * FF + col) = o1;
        }
    }
}

// =====================================================================
extern "C" void kernel_launch(void* const* d_in, const int* in_sizes, int n_in,
                              void* d_out, int out_size)
{
    const float* xl  = (const float*)d_in[0];
    const float* xh  = (const float*)d_in[1];
    const float* te  = (const float*)d_in[2];
    const float* Wq  = (const float*)d_in[3];
    const float* bq  = (const float*)d_in[4];
    const float* Wkh = (const float*)d_in[5];
    const float* bkh = (const float*)d_in[6];
    const float* Wvh = (const float*)d_in[7];
    const float* bvh = (const float*)d_in[8];
    const float* Wo  = (const float*)d_in[9];
    const float* bo  = (const float*)d_in[10];
    const float* Wf1 = (const float*)d_in[11];
    const float* bf1 = (const float*)d_in[12];
    const float* Wf2 = (const float*)d_in[13];
    const float* bf2 = (const float*)d_in[14];
    float* outp = (float*)d_out;

    const int smMega = 3 * 128 * HP * 2 + 4096;   // 108544

    cudaFuncSetAttribute(mega_kernel, cudaFuncAttributeMaxDynamicSharedMemorySize, smMega);

    conv_kernel<<<16, 256>>>(Wq, Wkh, Wvh, Wo, Wf1, Wf2);
    mega_kernel<<<BB * NN, 256, smMega>>>(outp, xl, xh, te, bq, bkh, bvh, bo, bf1, bf2);
}